// round 1
// baseline (speedup 1.0000x reference)
#include <cuda_runtime.h>
#include <cstdint>

// Problem constants
#define N_  16
#define T_  4096
#define I_  256
#define H_  512
#define C_  128     // number of chunks
#define L_  32      // chunk length, C_*L_ == T_

// -------- static device scratch (no allocation allowed) --------
__device__ float g_Wt [H_*H_];   // Whh^T  : Wt[k*H+j] = Whh[j*H+k]
__device__ float g_Wit[I_*H_];   // Wi^T   : Wit[i*H+j] = Wi[j*I+i]
__device__ float g_P0 [H_*H_];   // squaring ping
__device__ float g_P1 [H_*H_];   // squaring pong
__device__ float g_lend[C_*N_*H_]; // local state at each chunk end
__device__ float g_hb  [C_*N_*H_]; // true hidden at each chunk end

// monotonic grid barrier state (never reset -> deterministic across graph replays)
__device__ unsigned g_cnt = 0;
__device__ unsigned g_rel = 0;

__device__ __forceinline__ void grid_barrier_dev(unsigned total)
{
    __syncthreads();
    if (threadIdx.x == 0) {
        __threadfence();                       // make my stores visible
        unsigned my = atomicAdd(&g_cnt, 1u);   // my phase is derived from ticket
        if ((my % total) == total - 1u) {
            atomicAdd(&g_rel, 1u);             // release this generation
        } else {
            unsigned need = my / total + 1u;
            while (*((volatile unsigned*)&g_rel) < need) { }
        }
    }
    __syncthreads();
}

// -------- K0: transposes --------
__global__ void k_transpose(const float* __restrict__ Whh, const float* __restrict__ Wi)
{
    int idx = blockIdx.x * blockDim.x + threadIdx.x;
    if (idx < H_*H_) {
        int j = idx / H_, k = idx % H_;
        g_Wt[k*H_ + j] = Whh[idx];
    } else {
        int idx2 = idx - H_*H_;
        if (idx2 < H_*I_) {
            int j = idx2 / I_, i = idx2 % I_;
            g_Wit[i*H_ + j] = Wi[idx2];
        }
    }
}

// -------- generic fp32 GEMM: C = A[M,K] @ B[K,Nn] --------
// MODE 0: plain store (used for matrix squaring)
// MODE 1: RNN projection epilogue:
//   row r = n*T + s holds proj[n, s]. q[t] layout (stored into Cc=out0):
//     q[n,0]   = proj[n,0] + bias + initial[n]
//     q[n,s+1] = proj[n,s] + bias          (s <= T-2)
template<int MODE>
__global__ void __launch_bounds__(256, 2)
gemm_k(const float* __restrict__ A, const float* __restrict__ B,
       float* __restrict__ Cc, int M, int K, int Nn,
       const float* __restrict__ bias, const float* __restrict__ initial)
{
    __shared__ __align__(16) float As[16][68];  // [k][m], padded
    __shared__ __align__(16) float Bs[16][64];  // [k][n]

    const int tid = threadIdx.x;
    const int bm = blockIdx.y * 64;
    const int bn = blockIdx.x * 64;
    const int tx = tid & 15, ty = tid >> 4;

    const int arow = tid >> 2;          // 0..63
    const int ak   = (tid & 3) * 4;     // 0,4,8,12
    const int brow = tid >> 4;          // 0..15
    const int bcol = (tid & 15) * 4;    // 0..60

    float acc[4][4];
#pragma unroll
    for (int i = 0; i < 4; ++i)
#pragma unroll
        for (int jj = 0; jj < 4; ++jj) acc[i][jj] = 0.f;

    for (int kt = 0; kt < K; kt += 16) {
        float4 av = *(const float4*)&A[(size_t)(bm + arow) * K + kt + ak];
        As[ak+0][arow] = av.x;
        As[ak+1][arow] = av.y;
        As[ak+2][arow] = av.z;
        As[ak+3][arow] = av.w;
        *(float4*)&Bs[brow][bcol] = *(const float4*)&B[(size_t)(kt + brow) * Nn + bn + bcol];
        __syncthreads();
#pragma unroll
        for (int k = 0; k < 16; ++k) {
            float4 a = *(const float4*)&As[k][ty*4];
            float4 b = *(const float4*)&Bs[k][tx*4];
            acc[0][0]=fmaf(a.x,b.x,acc[0][0]); acc[0][1]=fmaf(a.x,b.y,acc[0][1]);
            acc[0][2]=fmaf(a.x,b.z,acc[0][2]); acc[0][3]=fmaf(a.x,b.w,acc[0][3]);
            acc[1][0]=fmaf(a.y,b.x,acc[1][0]); acc[1][1]=fmaf(a.y,b.y,acc[1][1]);
            acc[1][2]=fmaf(a.y,b.z,acc[1][2]); acc[1][3]=fmaf(a.y,b.w,acc[1][3]);
            acc[2][0]=fmaf(a.z,b.x,acc[2][0]); acc[2][1]=fmaf(a.z,b.y,acc[2][1]);
            acc[2][2]=fmaf(a.z,b.z,acc[2][2]); acc[2][3]=fmaf(a.z,b.w,acc[2][3]);
            acc[3][0]=fmaf(a.w,b.x,acc[3][0]); acc[3][1]=fmaf(a.w,b.y,acc[3][1]);
            acc[3][2]=fmaf(a.w,b.z,acc[3][2]); acc[3][3]=fmaf(a.w,b.w,acc[3][3]);
        }
        __syncthreads();
    }

    if (MODE == 0) {
#pragma unroll
        for (int i = 0; i < 4; ++i) {
            float4 v = make_float4(acc[i][0], acc[i][1], acc[i][2], acc[i][3]);
            *(float4*)&Cc[(size_t)(bm + ty*4 + i) * Nn + bn + tx*4] = v;
        }
    } else {
        float4 bv = *(const float4*)&bias[bn + tx*4];
#pragma unroll
        for (int i = 0; i < 4; ++i) {
            int r = bm + ty*4 + i;
            int s = r & (T_ - 1);     // T_ is power of two
            int n = r >> 12;          // r / T_
            float4 v = make_float4(acc[i][0]+bv.x, acc[i][1]+bv.y,
                                   acc[i][2]+bv.z, acc[i][3]+bv.w);
            if (s < T_ - 1)
                *(float4*)&Cc[((size_t)n*T_ + s + 1)*H_ + bn + tx*4] = v;
            if (s == 0) {
                float4 iv = *(const float4*)&initial[(size_t)n*H_ + bn + tx*4];
                float4 v0 = make_float4(v.x+iv.x, v.y+iv.y, v.z+iv.z, v.w+iv.w);
                *(float4*)&Cc[((size_t)n*T_)*H_ + bn + tx*4] = v0;
            }
        }
    }
}

// -------- K2: local scan per chunk (carry-in = 0), in place over q --------
// q holds q[t] on entry; holds l[t] (local states) on exit. Also writes lend.
__global__ void __launch_bounds__(512, 1)
k_local(const float* __restrict__ Wt, float* __restrict__ q, float* __restrict__ lend)
{
    __shared__ __align__(16) float hs[N_][H_];
    const int c = blockIdx.x;
    const int j = threadIdx.x;
    const int t0 = c * L_;

    float acc[N_];
#pragma unroll
    for (int n = 0; n < N_; ++n) {
        acc[n] = q[((size_t)n*T_ + t0)*H_ + j];   // l[t0] = q[t0]
        hs[n][j] = acc[n];
    }
    __syncthreads();

    for (int s = 1; s < L_; ++s) {
        const size_t t = (size_t)t0 + s;
#pragma unroll
        for (int n = 0; n < N_; ++n)
            acc[n] = q[((size_t)n*T_ + t)*H_ + j];
#pragma unroll 4
        for (int k4 = 0; k4 < H_/4; ++k4) {
            const int k = k4 * 4;
            float w0 = Wt[(k+0)*H_ + j];
            float w1 = Wt[(k+1)*H_ + j];
            float w2 = Wt[(k+2)*H_ + j];
            float w3 = Wt[(k+3)*H_ + j];
#pragma unroll
            for (int n = 0; n < N_; ++n) {
                float4 h = *(const float4*)&hs[n][k];
                acc[n] = fmaf(h.x, w0, acc[n]);
                acc[n] = fmaf(h.y, w1, acc[n]);
                acc[n] = fmaf(h.z, w2, acc[n]);
                acc[n] = fmaf(h.w, w3, acc[n]);
            }
        }
        __syncthreads();
#pragma unroll
        for (int n = 0; n < N_; ++n) {
            hs[n][j] = acc[n];
            q[((size_t)n*T_ + t)*H_ + j] = acc[n];
        }
        __syncthreads();
    }
#pragma unroll
    for (int n = 0; n < N_; ++n)
        lend[((size_t)c*N_ + n)*H_ + j] = acc[n];
}

// -------- K4: boundary scan (persistent, grid barrier) --------
// hb[0] = lend[0];  hb[c] = hb[c-1] @ ML^T + lend[c]   (ML = Whh^L, stored transposed)
__global__ void __launch_bounds__(128, 1)
k_bscan(const float* __restrict__ ML, const float* __restrict__ lend, float* __restrict__ hb)
{
    const int b   = blockIdx.x;
    const int tid = threadIdx.x;
    const unsigned total = gridDim.x;          // 64
    const int n = tid >> 3;                    // 0..15
    const int j = b * 8 + (tid & 7);           // 0..511

    // hb[0] = lend[0]   (64 CTAs * 128 threads = 8192 = N*H)
    {
        int idx = b * 128 + tid;
        __stcg(&hb[idx], lend[idx]);
    }
    grid_barrier_dev(total);

    for (int c = 1; c < C_; ++c) {
        const float4* hp4 = (const float4*)(hb + (size_t)(c-1)*N_*H_ + (size_t)n*H_);
        float a0 = 0.f, a1 = 0.f, a2 = 0.f, a3 = 0.f;
#pragma unroll 4
        for (int k4 = 0; k4 < H_/4; ++k4) {
            float4 h = __ldcg(&hp4[k4]);       // L2 path: written by peer CTAs
            const int k = k4 * 4;
            a0 = fmaf(h.x, ML[(size_t)(k+0)*H_ + j], a0);
            a1 = fmaf(h.y, ML[(size_t)(k+1)*H_ + j], a1);
            a2 = fmaf(h.z, ML[(size_t)(k+2)*H_ + j], a2);
            a3 = fmaf(h.w, ML[(size_t)(k+3)*H_ + j], a3);
        }
        float acc = lend[(size_t)c*N_*H_ + (size_t)n*H_ + j] + ((a0 + a1) + (a2 + a3));
        __stcg(&hb[(size_t)c*N_*H_ + (size_t)n*H_ + j], acc);
        grid_barrier_dev(total);
    }
}

// -------- K5: correction pass per chunk; finalize out0 (+ duplicate to out1) --------
// d[t0] = Whh * hb[c-1]; d[t] = Whh * d[t-1]; h[t] = l[t] + d[t]
__global__ void __launch_bounds__(512, 1)
k_corr(const float* __restrict__ Wt, const float* __restrict__ hb,
       float* __restrict__ out0, float* __restrict__ out1, int dup)
{
    const int c = blockIdx.x;
    const int j = threadIdx.x;

    if (c == 0) {   // chunk 0: local state IS the answer; just mirror to out1
        if (dup) {
            for (int s = 0; s < L_; ++s) {
#pragma unroll
                for (int n = 0; n < N_; ++n) {
                    size_t idx = ((size_t)n*T_ + s)*H_ + j;
                    out1[idx] = out0[idx];
                }
            }
        }
        return;
    }

    __shared__ __align__(16) float ds[N_][H_];
    const int t0 = c * L_;
#pragma unroll
    for (int n = 0; n < N_; ++n)
        ds[n][j] = hb[((size_t)(c-1)*N_ + n)*H_ + j];
    __syncthreads();

    for (int s = 0; s < L_; ++s) {
        const size_t t = (size_t)t0 + s;
        float acc[N_];
#pragma unroll
        for (int n = 0; n < N_; ++n) acc[n] = 0.f;
#pragma unroll 4
        for (int k4 = 0; k4 < H_/4; ++k4) {
            const int k = k4 * 4;
            float w0 = Wt[(k+0)*H_ + j];
            float w1 = Wt[(k+1)*H_ + j];
            float w2 = Wt[(k+2)*H_ + j];
            float w3 = Wt[(k+3)*H_ + j];
#pragma unroll
            for (int n = 0; n < N_; ++n) {
                float4 h = *(const float4*)&ds[n][k];
                acc[n] = fmaf(h.x, w0, acc[n]);
                acc[n] = fmaf(h.y, w1, acc[n]);
                acc[n] = fmaf(h.z, w2, acc[n]);
                acc[n] = fmaf(h.w, w3, acc[n]);
            }
        }
        __syncthreads();
#pragma unroll
        for (int n = 0; n < N_; ++n) {
            ds[n][j] = acc[n];                       // carry d forward
            size_t idx = ((size_t)n*T_ + t)*H_ + j;
            float v = out0[idx] + acc[n];            // h = l + d
            out0[idx] = v;
            if (dup) out1[idx] = v;
        }
        __syncthreads();
    }
}

// ----------------------------------------------------------------------------
extern "C" void kernel_launch(void* const* d_in, const int* in_sizes, int n_in,
                              void* d_out, int out_size)
{
    const float *x = nullptr, *initial = nullptr, *Wi = nullptr, *bi = nullptr, *Whh = nullptr;
    for (int i = 0; i < n_in; ++i) {
        switch (in_sizes[i]) {
            case N_*T_*I_: x       = (const float*)d_in[i]; break;  // 16,777,216
            case N_*H_:    initial = (const float*)d_in[i]; break;  // 8,192
            case H_*I_:    Wi      = (const float*)d_in[i]; break;  // 131,072
            case H_:       bi      = (const float*)d_in[i]; break;  // 512
            case H_*H_:    Whh     = (const float*)d_in[i]; break;  // 262,144
        }
    }
    // positional fallback (setup_inputs order: x, initial, Wi, bi, Whh)
    if (!x       && n_in > 0) x       = (const float*)d_in[0];
    if (!initial && n_in > 1) initial = (const float*)d_in[1];
    if (!Wi      && n_in > 2) Wi      = (const float*)d_in[2];
    if (!bi      && n_in > 3) bi      = (const float*)d_in[3];
    if (!Whh     && n_in > 4) Whh     = (const float*)d_in[4];

    float* out0 = (float*)d_out;
    const size_t NTH = (size_t)N_ * T_ * H_;
    int dup = ((size_t)out_size >= 2 * NTH) ? 1 : 0;
    float* out1 = out0 + NTH;

    float *Wt, *Wit, *P0, *P1, *lend, *hb;
    cudaGetSymbolAddress((void**)&Wt,   g_Wt);
    cudaGetSymbolAddress((void**)&Wit,  g_Wit);
    cudaGetSymbolAddress((void**)&P0,   g_P0);
    cudaGetSymbolAddress((void**)&P1,   g_P1);
    cudaGetSymbolAddress((void**)&lend, g_lend);
    cudaGetSymbolAddress((void**)&hb,   g_hb);

    // K0: transposes
    k_transpose<<<(H_*H_ + H_*I_ + 255)/256, 256>>>(Whh, Wi);

    // K1: projection q[t] into out0 (bias + initial fused; note q[t]=proj[t-1])
    {
        dim3 g(H_/64, (N_*T_)/64);
        gemm_k<1><<<g, 256>>>(x, Wit, out0, N_*T_, I_, H_, bi, initial);
    }

    // K3: ML^T = (Whh^T)^32 by 5 squarings (transposed rep squares directly)
    {
        dim3 g(H_/64, H_/64);
        gemm_k<0><<<g, 256>>>(Wt, Wt, P0, H_, H_, H_, nullptr, nullptr); // ^2
        gemm_k<0><<<g, 256>>>(P0, P0, P1, H_, H_, H_, nullptr, nullptr); // ^4
        gemm_k<0><<<g, 256>>>(P1, P1, P0, H_, H_, H_, nullptr, nullptr); // ^8
        gemm_k<0><<<g, 256>>>(P0, P0, P1, H_, H_, H_, nullptr, nullptr); // ^16
        gemm_k<0><<<g, 256>>>(P1, P1, P0, H_, H_, H_, nullptr, nullptr); // ^32
    }

    // K2: local scan (parallel over 128 chunks)
    k_local<<<C_, 512>>>(Wt, out0, lend);

    // K4: boundary scan (persistent kernel, 64 co-resident CTAs, grid barrier)
    k_bscan<<<64, 128>>>(P0, lend, hb);

    // K5: correction + finalize (+ duplicate output)
    k_corr<<<C_, 512>>>(Wt, hb, out0, out1, dup);
}